// round 6
// baseline (speedup 1.0000x reference)
#include <cuda_runtime.h>
#include <cuda_fp16.h>
#include <cstdint>

// ---------------------------------------------------------------------------
// Problem constants
// ---------------------------------------------------------------------------
#define N_IMG   16
#define C_IN    64
#define C_OUT   64
#define HH      128
#define WW      128
#define W_ELEMS (C_OUT * C_IN * 9)      // 36864
#define HP      130                      // padded H/W
#define XP_ELEMS (N_IMG * HP * HP * 64)  // fp16 padded NHWC scratch

// ---------------------------------------------------------------------------
// Persistent device scratch (zero-initialized; g_xp borders stay 0 forever)
// ---------------------------------------------------------------------------
__device__ double  g_part[32];
__device__ __half  g_xp[XP_ELEMS];        // [n][h+1][w+1][c]
__device__ __half  g_wB[9 * 64 * 64];     // [tap][oc][c]
__device__ float   g_beff[C_OUT];

// ---------------------------------------------------------------------------
// PTX helpers (sm_103-baseline: cp.async, ldmatrix, mma.sync)
// ---------------------------------------------------------------------------
__device__ __forceinline__ uint32_t smem_to_u32(const void* p) {
    uint32_t a;
    asm("{ .reg .u64 t; cvta.to.shared.u64 t, %1; cvt.u32.u64 %0, t; }"
        : "=r"(a) : "l"(p));
    return a;
}
__device__ __forceinline__ void cp16(uint32_t dst, const void* src) {
    asm volatile("cp.async.cg.shared.global [%0], [%1], 16;" :: "r"(dst), "l"(src));
}
__device__ __forceinline__ void cp_commit() {
    asm volatile("cp.async.commit_group;" ::: "memory");
}
__device__ __forceinline__ void cp_wait0() {
    asm volatile("cp.async.wait_group 0;" ::: "memory");
}
__device__ __forceinline__ void cp_wait1() {
    asm volatile("cp.async.wait_group 1;" ::: "memory");
}
__device__ __forceinline__ void ldsm_x4(uint32_t* r, uint32_t addr) {
    asm volatile("ldmatrix.sync.aligned.m8n8.x4.shared.b16 {%0,%1,%2,%3}, [%4];"
        : "=r"(r[0]), "=r"(r[1]), "=r"(r[2]), "=r"(r[3]) : "r"(addr));
}
__device__ __forceinline__ void mma16816(float* d, const uint32_t* a, const uint32_t* b) {
    asm volatile(
        "mma.sync.aligned.m16n8k16.row.col.f32.f16.f16.f32 "
        "{%0,%1,%2,%3}, {%4,%5,%6,%7}, {%8,%9}, {%0,%1,%2,%3};"
        : "+f"(d[0]), "+f"(d[1]), "+f"(d[2]), "+f"(d[3])
        : "r"(a[0]), "r"(a[1]), "r"(a[2]), "r"(a[3]), "r"(b[0]), "r"(b[1]));
}

// ---------------------------------------------------------------------------
// Kernel 1: partial |w| sums (fp64, deterministic)
// ---------------------------------------------------------------------------
__global__ void scale_part_kernel(const float* __restrict__ w,
                                  const float* __restrict__ wc) {
    int b = blockIdx.x;                  // 0..31
    const float* p = (b < 16) ? w : wc;
    int seg = b & 15;
    int start = seg * (W_ELEMS / 16);
    double s = 0.0;
    for (int i = start + threadIdx.x; i < start + W_ELEMS / 16; i += 256)
        s += (double)fabsf(p[i]);
    __shared__ double red[256];
    red[threadIdx.x] = s;
    __syncthreads();
    for (int off = 128; off > 0; off >>= 1) {
        if (threadIdx.x < off) red[threadIdx.x] += red[threadIdx.x + off];
        __syncthreads();
    }
    if (threadIdx.x == 0) g_part[b] = red[0];
}

// ---------------------------------------------------------------------------
// Kernel 2: finalize scales (redundant per block) + fuse ternary weights
// ---------------------------------------------------------------------------
__global__ void prep_kernel(const float* __restrict__ w,
                            const float* __restrict__ b,
                            const float* __restrict__ wc,
                            const float* __restrict__ bc,
                            const float* __restrict__ gate) {
    __shared__ float ssc[2];
    if (threadIdx.x < 2) {
        double s = 0.0;
        for (int i = 0; i < 16; ++i) s += g_part[threadIdx.x * 16 + i];
        ssc[threadIdx.x] = fmaxf((float)(s / (double)W_ELEMS), 1e-5f);
    }
    __syncthreads();
    int i = blockIdx.x * 256 + threadIdx.x;
    float g = 1.0f / (1.0f + expf(-gate[0]));
    if (i < W_ELEMS) {
        float s1 = ssc[0], s2 = ssc[1];
        float q1 = fminf(fmaxf(rintf(w[i]  / s1), -1.0f), 1.0f) * s1;
        float q2 = fminf(fmaxf(rintf(wc[i] / s2), -1.0f), 1.0f) * s2;
        int o = i / (C_IN * 9);
        int r = i - o * (C_IN * 9);
        int c = r / 9;
        int k = r - c * 9;
        g_wB[k * 4096 + o * 64 + c] = __float2half_rn(q1 + g * q2);
    }
    if (i < C_OUT)
        g_beff[i] = b[i] + g * bc[i];
}

// ---------------------------------------------------------------------------
// Kernel 3: NCHW fp32 -> padded NHWC fp16 transpose (float4 loads)
// ---------------------------------------------------------------------------
__global__ __launch_bounds__(256)
void transpose_kernel(const float* __restrict__ x) {
    const int w0 = blockIdx.x * 32;
    const int h  = blockIdx.y;
    const int n  = blockIdx.z;
    const int tid = threadIdx.x;

    __shared__ float s[32 * 65];
#pragma unroll
    for (int it = 0; it < 2; ++it) {
        int i = tid + it * 256;
        int c = i >> 3, j = i & 7;
        float4 v = *reinterpret_cast<const float4*>(
            x + (((size_t)(n * 64 + c)) * HH + h) * WW + w0 + j * 4);
        int wb = j * 4;
        s[(wb + 0) * 65 + c] = v.x;
        s[(wb + 1) * 65 + c] = v.y;
        s[(wb + 2) * 65 + c] = v.z;
        s[(wb + 3) * 65 + c] = v.w;
    }
    __syncthreads();

    int wc = tid >> 3;
    int cg = (tid & 7) * 8;
    alignas(16) __half h8[8];
#pragma unroll
    for (int j = 0; j < 8; ++j)
        h8[j] = __float2half_rn(s[wc * 65 + cg + j]);
    size_t dst = (((size_t)n * HP + (h + 1)) * HP + (w0 + wc + 1)) * 64 + cg;
    *reinterpret_cast<uint4*>(&g_xp[dst]) = *reinterpret_cast<const uint4*>(h8);
}

// ---------------------------------------------------------------------------
// Kernel 4: persistent implicit-GEMM conv via HMMA, m64n64 warp tiles
//   CTA = 128 CTAs, each owns a 16-output-row chunk of one image.
//   Tile = 4 output rows (M=512) x N=64 oc; 8 warps = 4 rows x 2 px-halves.
//   A lives in a 9-slot circular row ring (slot = rel % 9); sliding the
//   6-row window by 4 rows/tile stages only 4 new rows per tile.
// SMEM: B [0,73728) | A ring [73728, 223488) | bias [223488, 223744)
// ---------------------------------------------------------------------------
#define AROW_B   16640              // 130*128 bytes per padded row
#define A_OFF    73728
#define NSLOT    9
#define BIAS_OFF (A_OFF + NSLOT * AROW_B)   // 223488
#define SMEM_CONV (BIAS_OFF + 256)          // 223744

__device__ __forceinline__ void stage_row(uint32_t abuf, int slot,
                                          int n, int prow, int tid) {
    const char* src = reinterpret_cast<const char*>(
        g_xp + ((size_t)n * HP + prow) * HP * 64);
    uint32_t dst0 = abuf + slot * AROW_B;
    for (int i = tid; i < 1040; i += 256) {        // 1040 x 16B = one row
        int p = i >> 3, jj = i & 7;
        cp16(dst0 + p * 128 + ((jj ^ (p & 7)) << 4), src + (size_t)i * 16);
    }
}

__global__ __launch_bounds__(256, 1)
void conv_kernel(float* __restrict__ out) {
    extern __shared__ char sm[];
    const uint32_t base = smem_to_u32(sm);
    const int tid  = threadIdx.x;
    const int wid  = tid >> 5;
    const int lane = tid & 31;
    const int n  = blockIdx.x >> 3;          // image
    const int Y0 = (blockIdx.x & 7) * 16;    // chunk base output row

    float* bias_sm = reinterpret_cast<float*>(sm + BIAS_OFF);
    if (tid < 64) bias_sm[tid] = g_beff[tid];

    // Stage all 9 weight tiles (swizzle: chunk j of oc-row nr -> j^(nr&7))
    for (int k = tid; k < 4608; k += 256) {
        int q = k & 511;
        int nr = q >> 3, jj = q & 7;
        cp16(base + (k >> 9) * 8192 + nr * 128 + ((jj ^ (nr & 7)) << 4),
             reinterpret_cast<const char*>(g_wB) + (size_t)k * 16);
    }
    // Prologue: rows rel 0..5 (padded rows Y0..Y0+5)
    for (int r = 0; r < 6; ++r)
        stage_row(base + A_OFF, r, n, Y0 + r, tid);
    cp_commit();                              // group P0

    const int rw = wid >> 1;                  // output row within tile (0..3)
    const int m0 = (wid & 1) * 64;            // pixel half
    const int a_pl = lane & 15, a_hk = lane >> 4;
    const int b_nl = (lane & 7) + ((lane >> 4) << 3);
    const int b_hk = (lane >> 3) & 1;

#pragma unroll 1
    for (int j = 0; j < 4; ++j) {
        __syncthreads();                      // prev tile fully consumed
        if (j > 0) {
            int rel = 4 * j + 5;              // needed only at rw=3,dy=2
            stage_row(base + A_OFF, (rel >= 9) ? rel - 9 : rel, n, Y0 + rel, tid);
            cp_commit();                      // Ga_j
            cp_wait1();                       // Gb_{j-1} done (rows 4j+2..4j+4)
        } else {
            cp_wait0();                       // P0 done
        }
        __syncthreads();
        if (j < 3) {                          // prefetch next tile's rows
            for (int r = 0; r < 3; ++r) {
                int rel = 4 * j + 6 + r;
                stage_row(base + A_OFF, (rel >= 9) ? rel - 9 : rel, n, Y0 + rel, tid);
            }
            cp_commit();                      // Gb_j
        }

        float acc[4][8][4];
#pragma unroll
        for (int mi = 0; mi < 4; ++mi)
#pragma unroll
            for (int nj = 0; nj < 8; ++nj)
#pragma unroll
                for (int r = 0; r < 4; ++r) acc[mi][nj][r] = 0.0f;

#pragma unroll 1
        for (int dy = 0; dy < 3; ++dy) {
            if (dy == 2 && j > 0) {           // row 4j+5 must have landed
                if (j < 3) cp_wait1(); else cp_wait0();
                __syncthreads();
            }
            int rel = 4 * j + rw + dy;
            const uint32_t arow = base + A_OFF +
                ((rel >= 9) ? rel - 9 : rel) * AROW_B;
#pragma unroll 1
            for (int dx = 0; dx < 3; ++dx) {
                const uint32_t btap = base + (dy * 3 + dx) * 8192;
#pragma unroll 1
                for (int kc = 0; kc < 4; ++kc) {
                    uint32_t a[4][4];
#pragma unroll
                    for (int mi = 0; mi < 4; ++mi) {
                        int pix = m0 + mi * 16 + a_pl + dx;
                        ldsm_x4(a[mi], arow + pix * 128 +
                                (((2 * kc + a_hk) ^ (pix & 7)) << 4));
                    }
#pragma unroll
                    for (int nj = 0; nj < 4; ++nj) {
                        uint32_t b[4];
                        int nn = nj * 16 + b_nl;
                        ldsm_x4(b, btap + nn * 128 +
                                (((2 * kc + b_hk) ^ (b_nl & 7)) << 4));
#pragma unroll
                        for (int mi = 0; mi < 4; ++mi) {
                            mma16816(acc[mi][nj * 2 + 0], a[mi], b + 0);
                            mma16816(acc[mi][nj * 2 + 1], a[mi], b + 2);
                        }
                    }
                }
            }
        }

        // Epilogue: direct STG.32 from fragments, bias from SMEM
        {
            const int y = Y0 + 4 * j + rw;
            float* ob = out + (size_t)n * (64 * 16384) + (size_t)y * 128;
            const int pl = lane >> 2, c2 = (lane & 3) * 2;
#pragma unroll
            for (int mi = 0; mi < 4; ++mi) {
                int pbase = m0 + mi * 16 + pl;
#pragma unroll
                for (int nj = 0; nj < 8; ++nj) {
                    float b0 = bias_sm[nj * 8 + c2];
                    float b1 = bias_sm[nj * 8 + c2 + 1];
                    float* p0 = ob + (size_t)(nj * 8 + c2) * 16384;
                    p0[pbase]             = acc[mi][nj][0] + b0;
                    p0[16384 + pbase]     = acc[mi][nj][1] + b1;
                    p0[pbase + 8]         = acc[mi][nj][2] + b0;
                    p0[16384 + pbase + 8] = acc[mi][nj][3] + b1;
                }
            }
        }
    }
}

// ---------------------------------------------------------------------------
extern "C" void kernel_launch(void* const* d_in, const int* in_sizes, int n_in,
                              void* d_out, int out_size) {
    const float* x  = (const float*)d_in[0];
    const float* w  = (const float*)d_in[1];
    const float* b  = (const float*)d_in[2];
    const float* wc = (const float*)d_in[3];
    const float* bc = (const float*)d_in[4];
    const float* gt = (const float*)d_in[5];
    float* out = (float*)d_out;

    static bool attr_set = false;
    if (!attr_set) {
        cudaFuncSetAttribute(conv_kernel,
                             cudaFuncAttributeMaxDynamicSharedMemorySize, SMEM_CONV);
        attr_set = true;
    }

    scale_part_kernel<<<32, 256>>>(w, wc);
    prep_kernel<<<(W_ELEMS + 255) / 256, 256>>>(w, b, wc, bc, gt);
    transpose_kernel<<<dim3(4, HH, N_IMG), 256>>>(x);
    conv_kernel<<<128, 256, SMEM_CONV>>>(out);
}

// round 7
// speedup vs baseline: 1.0546x; 1.0546x over previous
#include <cuda_runtime.h>
#include <cuda_fp16.h>
#include <cstdint>

// ---------------------------------------------------------------------------
// Problem constants
// ---------------------------------------------------------------------------
#define N_IMG   16
#define C_IN    64
#define C_OUT   64
#define HH      128
#define WW      128
#define W_ELEMS (C_OUT * C_IN * 9)      // 36864
#define HP      130                      // padded H/W
#define XP_ELEMS (N_IMG * HP * HP * 64)  // fp16 padded NHWC scratch

// ---------------------------------------------------------------------------
// Persistent device scratch (zero-initialized; g_xp borders stay 0 forever)
// ---------------------------------------------------------------------------
__device__ double  g_part[32];
__device__ __half  g_xp[XP_ELEMS];        // [n][h+1][w+1][c]
__device__ __half  g_wB[9 * 64 * 64];     // [tap][oc][c]
__device__ float   g_beff[C_OUT];

// ---------------------------------------------------------------------------
// PTX helpers (sm_103-baseline: cp.async, ldmatrix, mma.sync)
// ---------------------------------------------------------------------------
__device__ __forceinline__ uint32_t smem_to_u32(const void* p) {
    uint32_t a;
    asm("{ .reg .u64 t; cvta.to.shared.u64 t, %1; cvt.u32.u64 %0, t; }"
        : "=r"(a) : "l"(p));
    return a;
}
__device__ __forceinline__ void cp16(uint32_t dst, const void* src) {
    asm volatile("cp.async.cg.shared.global [%0], [%1], 16;" :: "r"(dst), "l"(src));
}
__device__ __forceinline__ void cp_commit() {
    asm volatile("cp.async.commit_group;" ::: "memory");
}
__device__ __forceinline__ void cp_wait0() {
    asm volatile("cp.async.wait_group 0;" ::: "memory");
}
__device__ __forceinline__ void cp_wait1() {
    asm volatile("cp.async.wait_group 1;" ::: "memory");
}
__device__ __forceinline__ void ldsm_x4(uint32_t* r, uint32_t addr) {
    asm volatile("ldmatrix.sync.aligned.m8n8.x4.shared.b16 {%0,%1,%2,%3}, [%4];"
        : "=r"(r[0]), "=r"(r[1]), "=r"(r[2]), "=r"(r[3]) : "r"(addr));
}
__device__ __forceinline__ void mma16816(float* d, const uint32_t* a, const uint32_t* b) {
    asm volatile(
        "mma.sync.aligned.m16n8k16.row.col.f32.f16.f16.f32 "
        "{%0,%1,%2,%3}, {%4,%5,%6,%7}, {%8,%9}, {%0,%1,%2,%3};"
        : "+f"(d[0]), "+f"(d[1]), "+f"(d[2]), "+f"(d[3])
        : "r"(a[0]), "r"(a[1]), "r"(a[2]), "r"(a[3]), "r"(b[0]), "r"(b[1]));
}

// ---------------------------------------------------------------------------
// Kernel 1: fused  (blocks 0..31: fp64 |w| partial sums)
//                  (blocks 32..: NCHW fp32 -> padded NHWC fp16 transpose)
// ---------------------------------------------------------------------------
__global__ __launch_bounds__(256)
void transpose_scale_kernel(const float* __restrict__ x,
                            const float* __restrict__ w,
                            const float* __restrict__ wc) {
    const int tid = threadIdx.x;
    if (blockIdx.x < 32) {
        int b = blockIdx.x;
        const float* p = (b < 16) ? w : wc;
        int seg = b & 15;
        int start = seg * (W_ELEMS / 16);
        double s = 0.0;
        for (int i = start + tid; i < start + W_ELEMS / 16; i += 256)
            s += (double)fabsf(p[i]);
        __shared__ double red[256];
        red[tid] = s;
        __syncthreads();
        for (int off = 128; off > 0; off >>= 1) {
            if (tid < off) red[tid] += red[tid + off];
            __syncthreads();
        }
        if (tid == 0) g_part[b] = red[0];
        return;
    }

    const int idx = blockIdx.x - 32;
    const int w0 = (idx & 3) * 32;
    const int h  = (idx >> 2) & 127;
    const int n  = idx >> 9;

    __shared__ float s[32 * 65];
#pragma unroll
    for (int it = 0; it < 2; ++it) {
        int i = tid + it * 256;
        int c = i >> 3, j = i & 7;
        float4 v = *reinterpret_cast<const float4*>(
            x + (((size_t)(n * 64 + c)) * HH + h) * WW + w0 + j * 4);
        int wb = j * 4;
        s[(wb + 0) * 65 + c] = v.x;
        s[(wb + 1) * 65 + c] = v.y;
        s[(wb + 2) * 65 + c] = v.z;
        s[(wb + 3) * 65 + c] = v.w;
    }
    __syncthreads();

    int wcx = tid >> 3;
    int cg = (tid & 7) * 8;
    alignas(16) __half h8[8];
#pragma unroll
    for (int j = 0; j < 8; ++j)
        h8[j] = __float2half_rn(s[wcx * 65 + cg + j]);
    size_t dst = (((size_t)n * HP + (h + 1)) * HP + (w0 + wcx + 1)) * 64 + cg;
    *reinterpret_cast<uint4*>(&g_xp[dst]) = *reinterpret_cast<const uint4*>(h8);
}

// ---------------------------------------------------------------------------
// Kernel 2: finalize scales (redundant per block) + fuse ternary weights
// ---------------------------------------------------------------------------
__global__ void prep_kernel(const float* __restrict__ w,
                            const float* __restrict__ b,
                            const float* __restrict__ wc,
                            const float* __restrict__ bc,
                            const float* __restrict__ gate) {
    __shared__ float ssc[2];
    if (threadIdx.x < 2) {
        double s = 0.0;
        for (int i = 0; i < 16; ++i) s += g_part[threadIdx.x * 16 + i];
        ssc[threadIdx.x] = fmaxf((float)(s / (double)W_ELEMS), 1e-5f);
    }
    __syncthreads();
    int i = blockIdx.x * 256 + threadIdx.x;
    float g = 1.0f / (1.0f + expf(-gate[0]));
    if (i < W_ELEMS) {
        float s1 = ssc[0], s2 = ssc[1];
        float q1 = fminf(fmaxf(rintf(w[i]  / s1), -1.0f), 1.0f) * s1;
        float q2 = fminf(fmaxf(rintf(wc[i] / s2), -1.0f), 1.0f) * s2;
        int o = i / (C_IN * 9);
        int r = i - o * (C_IN * 9);
        int c = r / 9;
        int k = r - c * 9;
        g_wB[k * 4096 + o * 64 + c] = __float2half_rn(q1 + g * q2);
    }
    if (i < C_OUT)
        g_beff[i] = b[i] + g * bc[i];
}

// ---------------------------------------------------------------------------
// Kernel 3: implicit-GEMM conv via HMMA.
//   512 threads (16 warps, 4/SMSP).  CTA = 16-output-row chunk of one image.
//   Tile = 4 output rows (M=512) x N=64; warp = m32n64 (rw = wid>>2,
//   m0 = (wid&3)*32).  A in a 9-slot circular row ring; sliding the 6-row
//   input window by 4 rows/tile stages 4 new rows per tile.
// SMEM: B [0,73728) | A ring [73728, 223488) | bias [223488, 223744)
// ---------------------------------------------------------------------------
#define AROW_B   16640              // 130*128 bytes per padded row
#define A_OFF    73728
#define NSLOT    9
#define BIAS_OFF (A_OFF + NSLOT * AROW_B)   // 223488
#define SMEM_CONV (BIAS_OFF + 256)          // 223744

__device__ __forceinline__ void stage_row(uint32_t abuf, int slot,
                                          int n, int prow, int tid) {
    const char* src = reinterpret_cast<const char*>(
        g_xp + ((size_t)n * HP + prow) * HP * 64);
    uint32_t dst0 = abuf + slot * AROW_B;
    for (int i = tid; i < 1040; i += 512) {        // 1040 x 16B = one row
        int p = i >> 3, jj = i & 7;
        cp16(dst0 + p * 128 + ((jj ^ (p & 7)) << 4), src + (size_t)i * 16);
    }
}

__global__ __launch_bounds__(512, 1)
void conv_kernel(float* __restrict__ out) {
    extern __shared__ char sm[];
    const uint32_t base = smem_to_u32(sm);
    const int tid  = threadIdx.x;
    const int wid  = tid >> 5;
    const int lane = tid & 31;
    const int n  = blockIdx.x >> 3;          // image
    const int Y0 = (blockIdx.x & 7) * 16;    // chunk base output row

    float* bias_sm = reinterpret_cast<float*>(sm + BIAS_OFF);
    if (tid < 64) bias_sm[tid] = g_beff[tid];

    // Stage all 9 weight tiles (swizzle: chunk j of oc-row nr -> j^(nr&7))
    for (int k = tid; k < 4608; k += 512) {
        int q = k & 511;
        int nr = q >> 3, jj = q & 7;
        cp16(base + (k >> 9) * 8192 + nr * 128 + ((jj ^ (nr & 7)) << 4),
             reinterpret_cast<const char*>(g_wB) + (size_t)k * 16);
    }
    // Prologue: rows rel 0..5 (padded rows Y0..Y0+5)
    for (int r = 0; r < 6; ++r)
        stage_row(base + A_OFF, r, n, Y0 + r, tid);
    cp_commit();                              // group P0 (B + 6 rows)

    const int rw = wid >> 2;                  // output row within tile (0..3)
    const int m0 = (wid & 3) * 32;            // 32-pixel quadrant
    const int a_pl = lane & 15, a_hk = lane >> 4;
    const int b_nl = (lane & 7) + ((lane >> 4) << 3);
    const int b_hk = (lane >> 3) & 1;

#pragma unroll 1
    for (int j = 0; j < 4; ++j) {
        __syncthreads();                      // prev tile fully consumed
        if (j > 0) {
            int rel = 4 * j + 5;              // needed only at dy=2
            stage_row(base + A_OFF, (rel >= 9) ? rel - 9 : rel, n, Y0 + rel, tid);
            cp_commit();                      // Ga_j
            cp_wait1();                       // Gb_{j-1} done (rows 4j+2..4j+4)
        } else {
            cp_wait0();                       // P0 done
        }
        __syncthreads();
        if (j < 3) {                          // prefetch next tile's rows
            for (int r = 0; r < 3; ++r) {
                int rel = 4 * j + 6 + r;
                stage_row(base + A_OFF, (rel >= 9) ? rel - 9 : rel, n, Y0 + rel, tid);
            }
            cp_commit();                      // Gb_j
        }

        float acc[2][8][4];
#pragma unroll
        for (int mi = 0; mi < 2; ++mi)
#pragma unroll
            for (int nj = 0; nj < 8; ++nj)
#pragma unroll
                for (int r = 0; r < 4; ++r) acc[mi][nj][r] = 0.0f;

#pragma unroll 1
        for (int dy = 0; dy < 3; ++dy) {
            if (dy == 2 && j > 0) {           // row 4j+5 must have landed
                if (j < 3) cp_wait1(); else cp_wait0();
                __syncthreads();
            }
            int rel = 4 * j + rw + dy;
            const uint32_t arow = base + A_OFF +
                ((rel >= 9) ? rel - 9 : rel) * AROW_B;
#pragma unroll
            for (int dx = 0; dx < 3; ++dx) {
                const uint32_t btap = base + (dy * 3 + dx) * 8192;
#pragma unroll
                for (int kc = 0; kc < 4; ++kc) {
                    uint32_t a[2][4];
#pragma unroll
                    for (int mi = 0; mi < 2; ++mi) {
                        int pix = m0 + mi * 16 + a_pl + dx;
                        ldsm_x4(a[mi], arow + pix * 128 +
                                (((2 * kc + a_hk) ^ (pix & 7)) << 4));
                    }
#pragma unroll
                    for (int nj = 0; nj < 4; ++nj) {
                        uint32_t b[4];
                        int nn = nj * 16 + b_nl;
                        ldsm_x4(b, btap + nn * 128 +
                                (((2 * kc + b_hk) ^ (b_nl & 7)) << 4));
#pragma unroll
                        for (int mi = 0; mi < 2; ++mi) {
                            mma16816(acc[mi][nj * 2 + 0], a[mi], b + 0);
                            mma16816(acc[mi][nj * 2 + 1], a[mi], b + 2);
                        }
                    }
                }
            }
        }

        // Epilogue: direct STG.32 from fragments, bias from SMEM
        {
            const int y = Y0 + 4 * j + rw;
            float* ob = out + (size_t)n * (64 * 16384) + (size_t)y * 128;
            const int pl = lane >> 2, c2 = (lane & 3) * 2;
#pragma unroll
            for (int mi = 0; mi < 2; ++mi) {
                int pbase = m0 + mi * 16 + pl;
#pragma unroll
                for (int nj = 0; nj < 8; ++nj) {
                    float b0 = bias_sm[nj * 8 + c2];
                    float b1 = bias_sm[nj * 8 + c2 + 1];
                    float* p0 = ob + (size_t)(nj * 8 + c2) * 16384;
                    p0[pbase]             = acc[mi][nj][0] + b0;
                    p0[16384 + pbase]     = acc[mi][nj][1] + b1;
                    p0[pbase + 8]         = acc[mi][nj][2] + b0;
                    p0[16384 + pbase + 8] = acc[mi][nj][3] + b1;
                }
            }
        }
    }
}

// ---------------------------------------------------------------------------
extern "C" void kernel_launch(void* const* d_in, const int* in_sizes, int n_in,
                              void* d_out, int out_size) {
    const float* x  = (const float*)d_in[0];
    const float* w  = (const float*)d_in[1];
    const float* b  = (const float*)d_in[2];
    const float* wc = (const float*)d_in[3];
    const float* bc = (const float*)d_in[4];
    const float* gt = (const float*)d_in[5];
    float* out = (float*)d_out;

    static bool attr_set = false;
    if (!attr_set) {
        cudaFuncSetAttribute(conv_kernel,
                             cudaFuncAttributeMaxDynamicSharedMemorySize, SMEM_CONV);
        attr_set = true;
    }

    transpose_scale_kernel<<<8192 + 32, 256>>>(x, w, wc);
    prep_kernel<<<(W_ELEMS + 255) / 256, 256>>>(w, b, wc, bc, gt);
    conv_kernel<<<128, 512, SMEM_CONV>>>(out);
}